// round 4
// baseline (speedup 1.0000x reference)
#include <cuda_runtime.h>

// Problem constants
#define Bn  2
#define Tn  4096
#define Dn  512
#define Hn  8
#define DHn 64
#define BHn (Bn*Hn)

// Scratch (device globals: no allocation allowed)
__device__ float g_Q [BHn*Tn*DHn];   // [bh][t][dh]
__device__ float g_K [BHn*Tn*DHn];
__device__ float g_V [BHn*Tn*DHn];
__device__ float g_AO[Bn*Tn*Dn];     // [b][t][d]  attention output, pre-Wo
__device__ unsigned char g_mask[(size_t)Tn*Tn];  // canonical 0/1 mask
__device__ int g_mask_mode;                      // 0=uint8, 1=int32, 2=float32

// ---------------------------------------------------------------------------
// Mask dtype sniffing + canonicalization to uint8 (bool arrives as int32).
// ---------------------------------------------------------------------------
__global__ void detect_mask(const void* __restrict__ mask)
{
    if (threadIdx.x != 0 || blockIdx.x != 0) return;
    const unsigned* w = (const unsigned*)mask;
    bool is_i32 = true, is_f32 = true;
    for (int i = 0; i < 1024; i++) {
        unsigned v = w[i];
        if (v != 0u && v != 1u)           is_i32 = false;
        if (v != 0u && v != 0x3F800000u)  is_f32 = false;
    }
    g_mask_mode = is_i32 ? 1 : (is_f32 ? 2 : 0);
}

__global__ __launch_bounds__(256) void convert_mask(const void* __restrict__ mask)
{
    const int mode = g_mask_mode;
    const size_t n = (size_t)Tn * Tn;
    size_t i = (size_t)blockIdx.x * blockDim.x + threadIdx.x;
    size_t stride = (size_t)gridDim.x * blockDim.x;
    if (mode == 1) {
        const int* m = (const int*)mask;
        for (; i < n; i += stride) g_mask[i] = (m[i] != 0);
    } else if (mode == 2) {
        const float* m = (const float*)mask;
        for (; i < n; i += stride) g_mask[i] = (m[i] != 0.0f);
    } else {
        const unsigned char* m = (const unsigned char*)mask;
        for (; i < n; i += stride) g_mask[i] = (m[i] != 0);
    }
}

// ---------------------------------------------------------------------------
// Tiled SGEMM v2: C(128x64) per block, BK=16, 256 threads, 8x4 microtile.
// z selects Wq/Wk/Wv; output in head-major layout [bh][t][dh].
// ---------------------------------------------------------------------------
__global__ __launch_bounds__(256) void qkv_gemm(
    const float* __restrict__ X,
    const float* __restrict__ Wq, const float* __restrict__ Wk, const float* __restrict__ Wv,
    const float* __restrict__ bq, const float* __restrict__ bk, const float* __restrict__ bv)
{
    const float* W; const float* bias; float* out;
    if      (blockIdx.z == 0) { W = Wq; bias = bq; out = g_Q; }
    else if (blockIdx.z == 1) { W = Wk; bias = bk; out = g_K; }
    else                      { W = Wv; bias = bv; out = g_V; }

    __shared__ float As[16*132];  // transposed [k][m], 128 m + pad
    __shared__ float Bs[16*64];   // [k][n]

    const int tid = threadIdx.x;
    const int tx = tid & 15;      // 4 n each -> 64
    const int ty = tid >> 4;      // 8 m each -> 128
    const int m0 = blockIdx.y * 128, n0 = blockIdx.x * 64;

    const int lb_k = tid >> 4, lb_n4 = tid & 15;  // B loader: 16 x 16 float4

    float acc[8][4] = {};

    for (int k0 = 0; k0 < Dn; k0 += 16) {
        float4 av[2];
        #pragma unroll
        for (int r = 0; r < 2; r++) {
            int i = tid + 256*r;
            int m = i >> 2, c = i & 3;
            av[r] = ((const float4*)X)[(size_t)(m0+m)*(Dn/4) + (k0>>2) + c];
        }
        float4 bv4 = ((const float4*)W)[(size_t)(k0+lb_k)*(Dn/4) + (n0>>2) + lb_n4];
        __syncthreads();
        #pragma unroll
        for (int r = 0; r < 2; r++) {
            int i = tid + 256*r;
            int m = i >> 2, c = i & 3;
            As[(c*4+0)*132 + m] = av[r].x;
            As[(c*4+1)*132 + m] = av[r].y;
            As[(c*4+2)*132 + m] = av[r].z;
            As[(c*4+3)*132 + m] = av[r].w;
        }
        *(float4*)(Bs + lb_k*64 + lb_n4*4) = bv4;
        __syncthreads();
        #pragma unroll
        for (int k = 0; k < 16; k++) {
            float a[8];
            *(float4*)(a)   = *(const float4*)(As + k*132 + ty*8);
            *(float4*)(a+4) = *(const float4*)(As + k*132 + ty*8 + 4);
            float4 b = *(const float4*)(Bs + k*64 + tx*4);
            #pragma unroll
            for (int ii = 0; ii < 8; ii++) {
                acc[ii][0] += a[ii]*b.x;
                acc[ii][1] += a[ii]*b.y;
                acc[ii][2] += a[ii]*b.z;
                acc[ii][3] += a[ii]*b.w;
            }
        }
    }

    const int n = n0 + tx*4;
    float4 bb = *(const float4*)(bias + n);
    const int h = n / DHn, dh = n % DHn;   // 64-wide n tile = exactly one head
    #pragma unroll
    for (int ii = 0; ii < 8; ii++) {
        int m = m0 + ty*8 + ii;
        int b = m / Tn, t = m % Tn;
        float4 r = make_float4(acc[ii][0]+bb.x, acc[ii][1]+bb.y, acc[ii][2]+bb.z, acc[ii][3]+bb.w);
        *(float4*)(out + ((size_t)((b*Hn + h)*Tn + t))*DHn + dh) = r;
    }
}

// ---------------------------------------------------------------------------
// Output projection v2: g_AO(8192x512) @ Wo + bo -> d_out, same 128x64 tiling.
// ---------------------------------------------------------------------------
__global__ __launch_bounds__(256) void out_gemm(
    const float* __restrict__ W, const float* __restrict__ bias, float* __restrict__ out)
{
    __shared__ float As[16*132];
    __shared__ float Bs[16*64];

    const int tid = threadIdx.x;
    const int tx = tid & 15, ty = tid >> 4;
    const int m0 = blockIdx.y * 128, n0 = blockIdx.x * 64;
    const int lb_k = tid >> 4, lb_n4 = tid & 15;
    const float* X = g_AO;

    float acc[8][4] = {};

    for (int k0 = 0; k0 < Dn; k0 += 16) {
        float4 av[2];
        #pragma unroll
        for (int r = 0; r < 2; r++) {
            int i = tid + 256*r;
            int m = i >> 2, c = i & 3;
            av[r] = ((const float4*)X)[(size_t)(m0+m)*(Dn/4) + (k0>>2) + c];
        }
        float4 bv4 = ((const float4*)W)[(size_t)(k0+lb_k)*(Dn/4) + (n0>>2) + lb_n4];
        __syncthreads();
        #pragma unroll
        for (int r = 0; r < 2; r++) {
            int i = tid + 256*r;
            int m = i >> 2, c = i & 3;
            As[(c*4+0)*132 + m] = av[r].x;
            As[(c*4+1)*132 + m] = av[r].y;
            As[(c*4+2)*132 + m] = av[r].z;
            As[(c*4+3)*132 + m] = av[r].w;
        }
        *(float4*)(Bs + lb_k*64 + lb_n4*4) = bv4;
        __syncthreads();
        #pragma unroll
        for (int k = 0; k < 16; k++) {
            float a[8];
            *(float4*)(a)   = *(const float4*)(As + k*132 + ty*8);
            *(float4*)(a+4) = *(const float4*)(As + k*132 + ty*8 + 4);
            float4 b = *(const float4*)(Bs + k*64 + tx*4);
            #pragma unroll
            for (int ii = 0; ii < 8; ii++) {
                acc[ii][0] += a[ii]*b.x;
                acc[ii][1] += a[ii]*b.y;
                acc[ii][2] += a[ii]*b.z;
                acc[ii][3] += a[ii]*b.w;
            }
        }
    }

    const int n = n0 + tx*4;
    float4 bb = *(const float4*)(bias + n);
    #pragma unroll
    for (int ii = 0; ii < 8; ii++) {
        int m = m0 + ty*8 + ii;
        float4 r = make_float4(acc[ii][0]+bb.x, acc[ii][1]+bb.y, acc[ii][2]+bb.z, acc[ii][3]+bb.w);
        *(float4*)(out + (size_t)m*Dn + n) = r;
    }
}

// ---------------------------------------------------------------------------
// Flash attention v2, fp32. Block = 128 queries of one (b,h), 512 threads.
// S-phase: 32x16 thread grid, microtile 8q x 4k over a 128x128 S tile.
// PV-phase: 16x32 thread grid, microtile 4q x 4d over the 128x64 O tile.
// Row state (m, l, corr) lives in smem; P staged through smem.
// ---------------------------------------------------------------------------
#define BQ 128
#define BK 128

__global__ __launch_bounds__(512) void attn_kernel()
{
    extern __shared__ float sm[];
    float* Qs = sm;                  // [64][132] transposed: Qs[c][q]
    float* Ks = Qs + 64*132;         // [64][132] transposed: Ks[c][n]
    float* Vs = Ks + 64*132;         // [128][64] natural:    Vs[n][d]
    float* Ps = Vs + 128*64;         // [128][132] row-major: Ps[q][j]
    float* mS = Ps + 128*132;        // [128] running row max
    float* lS = mS + 128;            // [128] running row sum
    float* cS = lS + 128;            // [128] per-tile correction

    const int tid = threadIdx.x;
    // S-phase mapping: warp = 32 lanes spanning all 128 keys
    const int tk = tid & 31;         // keys: tk*4 .. tk*4+3
    const int tq = tid >> 5;         // warp id 0..15; queries tq*8 .. tq*8+7
    // PV-phase mapping
    const int td  = tid & 15;        // dims: td*4 .. td*4+3
    const int tq2 = tid >> 4;        // 0..31; queries tq2*4 .. tq2*4+3

    const int bh = blockIdx.y;
    const int q0 = blockIdx.x * BQ;
    const float* Qp = g_Q + ((size_t)bh*Tn + q0)*DHn;

    // Load Q transposed (c-outer mapping -> conflict-free STS), fold 1/8 scale
    for (int i = tid; i < 128*16; i += 512) {
        int c = i >> 7, q = i & 127;
        float4 v = ((const float4*)Qp)[q*16 + c];
        Qs[(c*4+0)*132 + q] = v.x * 0.125f;
        Qs[(c*4+1)*132 + q] = v.y * 0.125f;
        Qs[(c*4+2)*132 + q] = v.z * 0.125f;
        Qs[(c*4+3)*132 + q] = v.w * 0.125f;
    }
    if (tid < 128) { mS[tid] = -1e30f; lS[tid] = 0.0f; }

    float accO[4][4] = {};

    for (int j0 = 0; j0 < Tn; j0 += BK) {
        __syncthreads();  // prior PV reads of Ps/Vs/cS done; Q/m-init done (iter 0)

        const float* Kp = g_K + ((size_t)bh*Tn + j0)*DHn;
        const float* Vp = g_V + ((size_t)bh*Tn + j0)*DHn;
        // K transposed (c-outer, conflict-free STS)
        for (int i = tid; i < 128*16; i += 512) {
            int c = i >> 7, n = i & 127;
            float4 v = ((const float4*)Kp)[n*16 + c];
            Ks[(c*4+0)*132 + n] = v.x;
            Ks[(c*4+1)*132 + n] = v.y;
            Ks[(c*4+2)*132 + n] = v.z;
            Ks[(c*4+3)*132 + n] = v.w;
        }
        // V natural (linear, coalesced)
        for (int i = tid; i < 128*16; i += 512)
            ((float4*)Vs)[i] = ((const float4*)Vp)[i];
        __syncthreads();

        // ---- S = Q K^T (scaled via Q), 8x4 microtile ----
        float s[8][4] = {};
        #pragma unroll 8
        for (int k = 0; k < 64; k++) {
            float a[8];
            *(float4*)(a)   = *(const float4*)(Qs + k*132 + tq*8);      // broadcast
            *(float4*)(a+4) = *(const float4*)(Qs + k*132 + tq*8 + 4);  // broadcast
            float4 b = *(const float4*)(Ks + k*132 + tk*4);
            #pragma unroll
            for (int ii = 0; ii < 8; ii++) {
                s[ii][0] += a[ii]*b.x;
                s[ii][1] += a[ii]*b.y;
                s[ii][2] += a[ii]*b.z;
                s[ii][3] += a[ii]*b.w;
            }
        }

        // ---- mask + online softmax (full-warp row reductions) ----
        #pragma unroll
        for (int ii = 0; ii < 8; ii++) {
            const int row = tq*8 + ii;
            const int q = q0 + row;
            uchar4 mv = *(const uchar4*)(g_mask + (size_t)q*Tn + j0 + tk*4);
            if (!mv.x) s[ii][0] -= 1e9f;
            if (!mv.y) s[ii][1] -= 1e9f;
            if (!mv.z) s[ii][2] -= 1e9f;
            if (!mv.w) s[ii][3] -= 1e9f;

            float rm = fmaxf(fmaxf(s[ii][0], s[ii][1]), fmaxf(s[ii][2], s[ii][3]));
            rm = fmaxf(rm, __shfl_xor_sync(0xffffffffu, rm, 1));
            rm = fmaxf(rm, __shfl_xor_sync(0xffffffffu, rm, 2));
            rm = fmaxf(rm, __shfl_xor_sync(0xffffffffu, rm, 4));
            rm = fmaxf(rm, __shfl_xor_sync(0xffffffffu, rm, 8));
            rm = fmaxf(rm, __shfl_xor_sync(0xffffffffu, rm, 16));

            float m_old = mS[row];            // all lanes read (warp-own row)
            float m_new = fmaxf(m_old, rm);

            float ls = 0.0f;
            #pragma unroll
            for (int jj = 0; jj < 4; jj++) {
                float p = __expf(s[ii][jj] - m_new);
                s[ii][jj] = p;
                ls += p;
            }
            ls += __shfl_xor_sync(0xffffffffu, ls, 1);
            ls += __shfl_xor_sync(0xffffffffu, ls, 2);
            ls += __shfl_xor_sync(0xffffffffu, ls, 4);
            ls += __shfl_xor_sync(0xffffffffu, ls, 8);
            ls += __shfl_xor_sync(0xffffffffu, ls, 16);

            if (tk == 0) {
                float corr = __expf(m_old - m_new);
                mS[row] = m_new;
                cS[row] = corr;
                lS[row] = lS[row]*corr + ls;
            }
            *(float4*)(Ps + row*132 + tk*4) = make_float4(s[ii][0], s[ii][1], s[ii][2], s[ii][3]);
        }
        __syncthreads();

        // ---- O = O*corr + P V, 4q x 4d microtile ----
        #pragma unroll
        for (int z = 0; z < 4; z++) {
            float c = cS[tq2*4 + z];
            accO[z][0] *= c; accO[z][1] *= c; accO[z][2] *= c; accO[z][3] *= c;
        }
        #pragma unroll 8
        for (int j = 0; j < 128; j++) {
            float a[4];
            #pragma unroll
            for (int z = 0; z < 4; z++) a[z] = Ps[(tq2*4+z)*132 + j];   // broadcast
            float4 bv = *(const float4*)(Vs + j*64 + td*4);
            #pragma unroll
            for (int z = 0; z < 4; z++) {
                accO[z][0] += a[z]*bv.x;
                accO[z][1] += a[z]*bv.y;
                accO[z][2] += a[z]*bv.z;
                accO[z][3] += a[z]*bv.w;
            }
        }
    }

    // Finalize: normalize and write head-interleaved [b][t][d]
    const int b = bh >> 3, h = bh & 7;
    #pragma unroll
    for (int z = 0; z < 4; z++) {
        int row = tq2*4 + z;
        float inv = 1.0f / lS[row];
        int q = q0 + row;
        float4 r = make_float4(accO[z][0]*inv, accO[z][1]*inv, accO[z][2]*inv, accO[z][3]*inv);
        *(float4*)(g_AO + ((size_t)(b*Tn + q))*Dn + h*DHn + td*4) = r;
    }
}

// ---------------------------------------------------------------------------
extern "C" void kernel_launch(void* const* d_in, const int* in_sizes, int n_in,
                              void* d_out, int out_size)
{
    const float* x  = (const float*)d_in[0];
    const float* Wq = (const float*)d_in[1];
    const float* bq = (const float*)d_in[2];
    const float* Wk = (const float*)d_in[3];
    const float* bk = (const float*)d_in[4];
    const float* Wv = (const float*)d_in[5];
    const float* bv = (const float*)d_in[6];
    const float* Wo = (const float*)d_in[7];
    const float* bo = (const float*)d_in[8];
    const void*  mask = (const void*)d_in[9];
    float* out = (float*)d_out;

    const int attn_smem = (64*132 + 64*132 + 128*64 + 128*132 + 3*128) * 4;  // 169,472 B
    cudaFuncSetAttribute(attn_kernel, cudaFuncAttributeMaxDynamicSharedMemorySize, attn_smem);

    detect_mask<<<1, 32>>>(mask);
    convert_mask<<<1024, 256>>>(mask);
    qkv_gemm<<<dim3(Dn/64, (Bn*Tn)/128, 3), 256>>>(x, Wq, Wk, Wv, bq, bk, bv);
    attn_kernel<<<dim3(Tn/BQ, BHn), 512, attn_smem>>>();
    out_gemm<<<dim3(Dn/64, (Bn*Tn)/128), 256>>>(Wo, bo, out);
}

// round 5
// speedup vs baseline: 1.0553x; 1.0553x over previous
#include <cuda_runtime.h>

// Problem constants
#define Bn  2
#define Tn  4096
#define Dn  512
#define Hn  8
#define DHn 64
#define BHn (Bn*Hn)

typedef unsigned long long u64;

// Scratch (device globals: no allocation allowed)
__device__ float g_Q [BHn*Tn*DHn];   // [bh][t][dh]
__device__ float g_K [BHn*Tn*DHn];
__device__ float g_V [BHn*Tn*DHn];
__device__ float g_AO[Bn*Tn*Dn];     // [b][t][d]  attention output, pre-Wo
__device__ unsigned char g_mask[(size_t)Tn*Tn];  // canonical 0/1 mask
__device__ int g_mask_mode;                      // 0=uint8, 1=int32, 2=float32

// ---- packed f32x2 helpers ------------------------------------------------
__device__ __forceinline__ u64 pk2(float lo, float hi) {
    u64 d; asm("mov.b64 %0, {%1, %2};" : "=l"(d) : "f"(lo), "f"(hi)); return d;
}
__device__ __forceinline__ void upk2(float& lo, float& hi, u64 v) {
    asm("mov.b64 {%0, %1}, %2;" : "=f"(lo), "=f"(hi) : "l"(v));
}
__device__ __forceinline__ u64 fma2(u64 a, u64 b, u64 c) {
    u64 d; asm("fma.rn.f32x2 %0, %1, %2, %3;" : "=l"(d) : "l"(a), "l"(b), "l"(c)); return d;
}
__device__ __forceinline__ u64 mul2(u64 a, u64 b) {
    u64 d; asm("mul.rn.f32x2 %0, %1, %2;" : "=l"(d) : "l"(a), "l"(b)); return d;
}
__device__ __forceinline__ float hsum2(u64 v) {
    float lo, hi; upk2(lo, hi, v); return lo + hi;
}

// ---------------------------------------------------------------------------
// Mask dtype sniffing + canonicalization to uint8 (bool arrives as int32).
// ---------------------------------------------------------------------------
__global__ void detect_mask(const void* __restrict__ mask)
{
    if (threadIdx.x != 0 || blockIdx.x != 0) return;
    const unsigned* w = (const unsigned*)mask;
    bool is_i32 = true, is_f32 = true;
    for (int i = 0; i < 1024; i++) {
        unsigned v = w[i];
        if (v != 0u && v != 1u)           is_i32 = false;
        if (v != 0u && v != 0x3F800000u)  is_f32 = false;
    }
    g_mask_mode = is_i32 ? 1 : (is_f32 ? 2 : 0);
}

__global__ __launch_bounds__(256) void convert_mask(const void* __restrict__ mask)
{
    const int mode = g_mask_mode;
    const size_t n = (size_t)Tn * Tn;
    size_t i = (size_t)blockIdx.x * blockDim.x + threadIdx.x;
    size_t stride = (size_t)gridDim.x * blockDim.x;
    if (mode == 1) {
        const int* m = (const int*)mask;
        for (; i < n; i += stride) g_mask[i] = (m[i] != 0);
    } else if (mode == 2) {
        const float* m = (const float*)mask;
        for (; i < n; i += stride) g_mask[i] = (m[i] != 0.0f);
    } else {
        const unsigned char* m = (const unsigned char*)mask;
        for (; i < n; i += stride) g_mask[i] = (m[i] != 0);
    }
}

// ---------------------------------------------------------------------------
// SGEMM with f32x2: C(128x64) per block, BK=16, 256 threads.
// Thread (tx,ty): rows m = ty+16z (z<8), cols n = tx+16w (w<4).
// A natural [m][18], B transposed [n][18]; accumulate packed along k.
// ---------------------------------------------------------------------------
#define GS_A (128*18)
#define GS_B (64*18)

__device__ __forceinline__ void gemm_core(
    const float* __restrict__ X, const float* __restrict__ W,
    float* As, float* Bt, int m0, int n0, u64 acc[8][4])
{
    const int tid = threadIdx.x;
    const int lb_k = tid >> 4, lb_n4 = tid & 15;

    for (int k0 = 0; k0 < Dn; k0 += 16) {
        float4 av[2];
        #pragma unroll
        for (int r = 0; r < 2; r++) {
            int i = tid + 256*r;
            int m = i >> 2, c = i & 3;
            av[r] = ((const float4*)X)[(size_t)(m0+m)*(Dn/4) + (k0>>2) + c];
        }
        float4 bv4 = ((const float4*)W)[(size_t)(k0+lb_k)*(Dn/4) + (n0>>2) + lb_n4];
        __syncthreads();
        #pragma unroll
        for (int r = 0; r < 2; r++) {
            int i = tid + 256*r;
            int m = i >> 2, c = i & 3;
            *(u64*)(As + m*18 + 4*c)     = pk2(av[r].x, av[r].y);
            *(u64*)(As + m*18 + 4*c + 2) = pk2(av[r].z, av[r].w);
        }
        Bt[(4*lb_n4+0)*18 + lb_k] = bv4.x;
        Bt[(4*lb_n4+1)*18 + lb_k] = bv4.y;
        Bt[(4*lb_n4+2)*18 + lb_k] = bv4.z;
        Bt[(4*lb_n4+3)*18 + lb_k] = bv4.w;
        __syncthreads();

        const int tx = tid & 15, ty = tid >> 4;
        #pragma unroll
        for (int k2 = 0; k2 < 8; k2++) {
            u64 a[8], b[4];
            #pragma unroll
            for (int z = 0; z < 8; z++) a[z] = *(const u64*)(As + (ty+16*z)*18 + 2*k2);
            #pragma unroll
            for (int w = 0; w < 4; w++) b[w] = *(const u64*)(Bt + (tx+16*w)*18 + 2*k2);
            #pragma unroll
            for (int z = 0; z < 8; z++)
                #pragma unroll
                for (int w = 0; w < 4; w++)
                    acc[z][w] = fma2(a[z], b[w], acc[z][w]);
        }
    }
}

__global__ __launch_bounds__(256) void qkv_gemm(
    const float* __restrict__ X,
    const float* __restrict__ Wq, const float* __restrict__ Wk, const float* __restrict__ Wv,
    const float* __restrict__ bq, const float* __restrict__ bk, const float* __restrict__ bv)
{
    const float* W; const float* bias; float* out;
    if      (blockIdx.z == 0) { W = Wq; bias = bq; out = g_Q; }
    else if (blockIdx.z == 1) { W = Wk; bias = bk; out = g_K; }
    else                      { W = Wv; bias = bv; out = g_V; }

    __shared__ float As[GS_A];
    __shared__ float Bt[GS_B];

    const int tid = threadIdx.x;
    const int tx = tid & 15, ty = tid >> 4;
    const int m0 = blockIdx.y * 128, n0 = blockIdx.x * 64;

    u64 acc[8][4] = {};
    gemm_core(X, W, As, Bt, m0, n0, acc);

    const int h = n0 / DHn;   // 64-wide n tile = one head
    #pragma unroll
    for (int w = 0; w < 4; w++) {
        int dh = tx + 16*w;
        float bb = bias[n0 + dh];
        #pragma unroll
        for (int z = 0; z < 8; z++) {
            int m = m0 + ty + 16*z;
            int b = m / Tn, t = m % Tn;
            out[((size_t)((b*Hn + h)*Tn + t))*DHn + dh] = hsum2(acc[z][w]) + bb;
        }
    }
}

__global__ __launch_bounds__(256) void out_gemm(
    const float* __restrict__ W, const float* __restrict__ bias, float* __restrict__ out)
{
    __shared__ float As[GS_A];
    __shared__ float Bt[GS_B];

    const int tid = threadIdx.x;
    const int tx = tid & 15, ty = tid >> 4;
    const int m0 = blockIdx.y * 128, n0 = blockIdx.x * 64;

    u64 acc[8][4] = {};
    gemm_core(g_AO, W, As, Bt, m0, n0, acc);

    #pragma unroll
    for (int w = 0; w < 4; w++) {
        int n = n0 + tx + 16*w;
        float bb = bias[n];
        #pragma unroll
        for (int z = 0; z < 8; z++) {
            int m = m0 + ty + 16*z;
            out[(size_t)m*Dn + n] = hsum2(acc[z][w]) + bb;
        }
    }
}

// ---------------------------------------------------------------------------
// Flash attention v3, fp32 via f32x2. Block = 64 queries, 256 threads.
// Thread (tx,ty): S rows q=ty+16z (z<4), cols n=tx+16w (w<4); PV cols d=tx+16w.
// Qs/Ks natural [64][66]; Vt transposed [d][66]; P [q][66]. Packed along k/j.
// ---------------------------------------------------------------------------
__global__ __launch_bounds__(256) void attn_kernel()
{
    extern __shared__ float sm[];
    float* Qs = sm;              // [64][66] natural
    float* Ks = Qs + 64*66;      // [64][66] natural
    float* Vt = Ks + 64*66;      // [64][66] transposed: Vt[d][j]
    float* Ps = Vt + 64*66;      // [64][66] row-major:  Ps[q][j]
    float* mS = Ps + 64*66;      // [64]
    float* lS = mS + 64;         // [64]
    float* cS = lS + 64;         // [64]

    const int tid = threadIdx.x;
    const int tx = tid & 15, ty = tid >> 4;
    const int bh = blockIdx.y;
    const int q0 = blockIdx.x * 64;

    const float* Qp = g_Q + ((size_t)bh*Tn + q0)*DHn;

    // Q natural, fold 1/8 scale; u64 stores (8B-aligned: 264q+16c)
    for (int i = tid; i < 64*16; i += 256) {
        int q = i >> 4, c = i & 15;
        float4 v = ((const float4*)Qp)[q*16 + c];
        *(u64*)(Qs + q*66 + 4*c)     = pk2(v.x*0.125f, v.y*0.125f);
        *(u64*)(Qs + q*66 + 4*c + 2) = pk2(v.z*0.125f, v.w*0.125f);
    }
    if (tid < 64) { mS[tid] = -1e30f; lS[tid] = 0.0f; }

    u64 accO[4][4] = {};

    for (int j0 = 0; j0 < Tn; j0 += 64) {
        __syncthreads();  // prior PV reads of Ps/Vt complete; Q/state init done

        const float* Kp = g_K + ((size_t)bh*Tn + j0)*DHn;
        const float* Vp = g_V + ((size_t)bh*Tn + j0)*DHn;
        for (int i = tid; i < 64*16; i += 256) {
            int n = i >> 4, c = i & 15;
            float4 kv = ((const float4*)Kp)[n*16 + c];
            *(u64*)(Ks + n*66 + 4*c)     = pk2(kv.x, kv.y);
            *(u64*)(Ks + n*66 + 4*c + 2) = pk2(kv.z, kv.w);
            float4 vv = ((const float4*)Vp)[n*16 + c];  // row n=j, cols 4c..
            Vt[(4*c+0)*66 + n] = vv.x;
            Vt[(4*c+1)*66 + n] = vv.y;
            Vt[(4*c+2)*66 + n] = vv.z;
            Vt[(4*c+3)*66 + n] = vv.w;
        }
        __syncthreads();

        // ---- S = Q K^T, packed along k ----
        u64 s2[4][4] = {};
        #pragma unroll 8
        for (int c2 = 0; c2 < 32; c2++) {
            u64 a[4], b[4];
            #pragma unroll
            for (int z = 0; z < 4; z++) a[z] = *(const u64*)(Qs + (ty+16*z)*66 + 2*c2);
            #pragma unroll
            for (int w = 0; w < 4; w++) b[w] = *(const u64*)(Ks + (tx+16*w)*66 + 2*c2);
            #pragma unroll
            for (int z = 0; z < 4; z++)
                #pragma unroll
                for (int w = 0; w < 4; w++)
                    s2[z][w] = fma2(a[z], b[w], s2[z][w]);
        }

        // ---- mask + online softmax ----
        #pragma unroll
        for (int z = 0; z < 4; z++) {
            const int row = ty + 16*z;
            const int q = q0 + row;
            const unsigned char* mrow = g_mask + (size_t)q*Tn + j0;
            float s[4];
            #pragma unroll
            for (int w = 0; w < 4; w++) {
                s[w] = hsum2(s2[z][w]);
                if (!mrow[tx + 16*w]) s[w] -= 1e9f;
            }
            float rm = fmaxf(fmaxf(s[0], s[1]), fmaxf(s[2], s[3]));
            rm = fmaxf(rm, __shfl_xor_sync(0xffffffffu, rm, 1));
            rm = fmaxf(rm, __shfl_xor_sync(0xffffffffu, rm, 2));
            rm = fmaxf(rm, __shfl_xor_sync(0xffffffffu, rm, 4));
            rm = fmaxf(rm, __shfl_xor_sync(0xffffffffu, rm, 8));

            float m_old = mS[row];
            float m_new = fmaxf(m_old, rm);

            float ls = 0.0f;
            #pragma unroll
            for (int w = 0; w < 4; w++) {
                float p = __expf(s[w] - m_new);
                s[w] = p;
                ls += p;
            }
            ls += __shfl_xor_sync(0xffffffffu, ls, 1);
            ls += __shfl_xor_sync(0xffffffffu, ls, 2);
            ls += __shfl_xor_sync(0xffffffffu, ls, 4);
            ls += __shfl_xor_sync(0xffffffffu, ls, 8);

            if (tx == 0) {
                float corr = __expf(m_old - m_new);
                mS[row] = m_new;
                cS[row] = corr;
                lS[row] = lS[row]*corr + ls;
            }
            #pragma unroll
            for (int w = 0; w < 4; w++) Ps[row*66 + tx + 16*w] = s[w];
        }
        __syncthreads();

        // ---- O = O*corr + P V, packed along j ----
        #pragma unroll
        for (int z = 0; z < 4; z++) {
            u64 cc = pk2(cS[ty+16*z], cS[ty+16*z]);
            #pragma unroll
            for (int w = 0; w < 4; w++) accO[z][w] = mul2(accO[z][w], cc);
        }
        #pragma unroll 8
        for (int j2 = 0; j2 < 32; j2++) {
            u64 a[4], b[4];
            #pragma unroll
            for (int z = 0; z < 4; z++) a[z] = *(const u64*)(Ps + (ty+16*z)*66 + 2*j2);
            #pragma unroll
            for (int w = 0; w < 4; w++) b[w] = *(const u64*)(Vt + (tx+16*w)*66 + 2*j2);
            #pragma unroll
            for (int z = 0; z < 4; z++)
                #pragma unroll
                for (int w = 0; w < 4; w++)
                    accO[z][w] = fma2(a[z], b[w], accO[z][w]);
        }
    }

    // Finalize: normalize, write head-interleaved [b][t][d]
    const int b = bh >> 3, h = bh & 7;
    #pragma unroll
    for (int z = 0; z < 4; z++) {
        int row = ty + 16*z;
        float inv = 1.0f / lS[row];
        int q = q0 + row;
        #pragma unroll
        for (int w = 0; w < 4; w++)
            g_AO[((size_t)(b*Tn + q))*Dn + h*DHn + tx + 16*w] = hsum2(accO[z][w]) * inv;
    }
}

// ---------------------------------------------------------------------------
extern "C" void kernel_launch(void* const* d_in, const int* in_sizes, int n_in,
                              void* d_out, int out_size)
{
    const float* x  = (const float*)d_in[0];
    const float* Wq = (const float*)d_in[1];
    const float* bq = (const float*)d_in[2];
    const float* Wk = (const float*)d_in[3];
    const float* bk = (const float*)d_in[4];
    const float* Wv = (const float*)d_in[5];
    const float* bv = (const float*)d_in[6];
    const float* Wo = (const float*)d_in[7];
    const float* bo = (const float*)d_in[8];
    const void*  mask = (const void*)d_in[9];
    float* out = (float*)d_out;

    const int attn_smem = (4*64*66 + 3*64) * 4;  // 68,352 B
    cudaFuncSetAttribute(attn_kernel, cudaFuncAttributeMaxDynamicSharedMemorySize, attn_smem);

    detect_mask<<<1, 32>>>(mask);
    convert_mask<<<1024, 256>>>(mask);
    qkv_gemm<<<dim3(Dn/64, (Bn*Tn)/128, 3), 256>>>(x, Wq, Wk, Wv, bq, bk, bv);
    attn_kernel<<<dim3(Tn/64, BHn), 256, attn_smem>>>();
    out_gemm<<<dim3(Dn/64, (Bn*Tn)/128), 256>>>(Wo, bo, out);
}

// round 8
// speedup vs baseline: 1.9590x; 1.8564x over previous
#include <cuda_runtime.h>

// Problem constants
#define Bn  2
#define Tn  4096
#define Dn  512
#define Hn  8
#define DHn 64
#define BHn (Bn*Hn)

typedef unsigned long long u64;
typedef unsigned char uchar;

// Scratch (device globals: no allocation allowed)
__device__ float g_Q [BHn*Tn*DHn];   // [bh][t][dh]
__device__ float g_K [BHn*Tn*DHn];
__device__ float g_V [BHn*Tn*DHn];
__device__ float g_AO[Bn*Tn*Dn];     // [b][t][d]  attention output, pre-Wo
__device__ uchar g_mask[(size_t)Tn*Tn];  // canonical 0/1 mask
__device__ int g_mask_mode;              // 0=uint8, 1=int32, 2=float32

// ---- packed f32x2 helpers (GEMMs, kept from round 5) ----------------------
__device__ __forceinline__ u64 pk2(float lo, float hi) {
    u64 d; asm("mov.b64 %0, {%1, %2};" : "=l"(d) : "f"(lo), "f"(hi)); return d;
}
__device__ __forceinline__ void upk2(float& lo, float& hi, u64 v) {
    asm("mov.b64 {%0, %1}, %2;" : "=f"(lo), "=f"(hi) : "l"(v));
}
__device__ __forceinline__ u64 fma2(u64 a, u64 b, u64 c) {
    u64 d; asm("fma.rn.f32x2 %0, %1, %2, %3;" : "=l"(d) : "l"(a), "l"(b), "l"(c)); return d;
}
__device__ __forceinline__ float hsum2(u64 v) {
    float lo, hi; upk2(lo, hi, v); return lo + hi;
}

// ---- tf32 helpers ----------------------------------------------------------
__device__ __forceinline__ float tf32r(float x) {
    float r; asm("cvt.rna.tf32.f32 %0, %1;" : "=f"(r) : "f"(x)); return r;
}
__device__ __forceinline__ void mma_tf32(float c[4],
    unsigned a0, unsigned a1, unsigned a2, unsigned a3, unsigned b0, unsigned b1)
{
    asm volatile(
        "mma.sync.aligned.m16n8k8.row.col.f32.tf32.tf32.f32 "
        "{%0,%1,%2,%3}, {%4,%5,%6,%7}, {%8,%9}, {%0,%1,%2,%3};"
        : "+f"(c[0]), "+f"(c[1]), "+f"(c[2]), "+f"(c[3])
        : "r"(a0), "r"(a1), "r"(a2), "r"(a3), "r"(b0), "r"(b1));
}
__device__ __forceinline__ unsigned fbits(float x) { return __float_as_uint(x); }

// ---------------------------------------------------------------------------
// Mask dtype sniffing + canonicalization to uint8 (bool arrives as int32).
// ---------------------------------------------------------------------------
__global__ void detect_mask(const void* __restrict__ mask)
{
    if (threadIdx.x != 0 || blockIdx.x != 0) return;
    const unsigned* w = (const unsigned*)mask;
    bool is_i32 = true, is_f32 = true;
    for (int i = 0; i < 1024; i++) {
        unsigned v = w[i];
        if (v != 0u && v != 1u)           is_i32 = false;
        if (v != 0u && v != 0x3F800000u)  is_f32 = false;
    }
    g_mask_mode = is_i32 ? 1 : (is_f32 ? 2 : 0);
}

__global__ __launch_bounds__(256) void convert_mask(const void* __restrict__ mask)
{
    const int mode = g_mask_mode;
    const size_t n = (size_t)Tn * Tn;
    size_t i = (size_t)blockIdx.x * blockDim.x + threadIdx.x;
    size_t stride = (size_t)gridDim.x * blockDim.x;
    if (mode == 1) {
        const int* m = (const int*)mask;
        for (; i < n; i += stride) g_mask[i] = (m[i] != 0);
    } else if (mode == 2) {
        const float* m = (const float*)mask;
        for (; i < n; i += stride) g_mask[i] = (m[i] != 0.0f);
    } else {
        const uchar* m = (const uchar*)mask;
        for (; i < n; i += stride) g_mask[i] = (m[i] != 0);
    }
}

// ---------------------------------------------------------------------------
// SGEMM with f32x2 (round-5, known correct): C(128x64)/block, BK=16, 256 thr.
// ---------------------------------------------------------------------------
#define GS_A (128*18)
#define GS_B (64*18)

__device__ __forceinline__ void gemm_core(
    const float* __restrict__ X, const float* __restrict__ W,
    float* As, float* Bt, int m0, int n0, u64 acc[8][4])
{
    const int tid = threadIdx.x;
    const int lb_k = tid >> 4, lb_n4 = tid & 15;

    for (int k0 = 0; k0 < Dn; k0 += 16) {
        float4 av[2];
        #pragma unroll
        for (int r = 0; r < 2; r++) {
            int i = tid + 256*r;
            int m = i >> 2, c = i & 3;
            av[r] = ((const float4*)X)[(size_t)(m0+m)*(Dn/4) + (k0>>2) + c];
        }
        float4 bv4 = ((const float4*)W)[(size_t)(k0+lb_k)*(Dn/4) + (n0>>2) + lb_n4];
        __syncthreads();
        #pragma unroll
        for (int r = 0; r < 2; r++) {
            int i = tid + 256*r;
            int m = i >> 2, c = i & 3;
            *(u64*)(As + m*18 + 4*c)     = pk2(av[r].x, av[r].y);
            *(u64*)(As + m*18 + 4*c + 2) = pk2(av[r].z, av[r].w);
        }
        Bt[(4*lb_n4+0)*18 + lb_k] = bv4.x;
        Bt[(4*lb_n4+1)*18 + lb_k] = bv4.y;
        Bt[(4*lb_n4+2)*18 + lb_k] = bv4.z;
        Bt[(4*lb_n4+3)*18 + lb_k] = bv4.w;
        __syncthreads();

        const int tx = tid & 15, ty = tid >> 4;
        #pragma unroll
        for (int k2 = 0; k2 < 8; k2++) {
            u64 a[8], b[4];
            #pragma unroll
            for (int z = 0; z < 8; z++) a[z] = *(const u64*)(As + (ty+16*z)*18 + 2*k2);
            #pragma unroll
            for (int w = 0; w < 4; w++) b[w] = *(const u64*)(Bt + (tx+16*w)*18 + 2*k2);
            #pragma unroll
            for (int z = 0; z < 8; z++)
                #pragma unroll
                for (int w = 0; w < 4; w++)
                    acc[z][w] = fma2(a[z], b[w], acc[z][w]);
        }
    }
}

__global__ __launch_bounds__(256) void qkv_gemm(
    const float* __restrict__ X,
    const float* __restrict__ Wq, const float* __restrict__ Wk, const float* __restrict__ Wv,
    const float* __restrict__ bq, const float* __restrict__ bk, const float* __restrict__ bv)
{
    const float* W; const float* bias; float* out;
    if      (blockIdx.z == 0) { W = Wq; bias = bq; out = g_Q; }
    else if (blockIdx.z == 1) { W = Wk; bias = bk; out = g_K; }
    else                      { W = Wv; bias = bv; out = g_V; }

    __shared__ float As[GS_A];
    __shared__ float Bt[GS_B];

    const int tid = threadIdx.x;
    const int tx = tid & 15, ty = tid >> 4;
    const int m0 = blockIdx.y * 128, n0 = blockIdx.x * 64;

    u64 acc[8][4] = {};
    gemm_core(X, W, As, Bt, m0, n0, acc);

    const int h = n0 / DHn;
    #pragma unroll
    for (int w = 0; w < 4; w++) {
        int dh = tx + 16*w;
        float bb = bias[n0 + dh];
        #pragma unroll
        for (int z = 0; z < 8; z++) {
            int m = m0 + ty + 16*z;
            int b = m / Tn, t = m % Tn;
            out[((size_t)((b*Hn + h)*Tn + t))*DHn + dh] = hsum2(acc[z][w]) + bb;
        }
    }
}

__global__ __launch_bounds__(256) void out_gemm(
    const float* __restrict__ W, const float* __restrict__ bias, float* __restrict__ out)
{
    __shared__ float As[GS_A];
    __shared__ float Bt[GS_B];

    const int tid = threadIdx.x;
    const int tx = tid & 15, ty = tid >> 4;
    const int m0 = blockIdx.y * 128, n0 = blockIdx.x * 64;

    u64 acc[8][4] = {};
    gemm_core(g_AO, W, As, Bt, m0, n0, acc);

    #pragma unroll
    for (int w = 0; w < 4; w++) {
        int n = n0 + tx + 16*w;
        float bb = bias[n];
        #pragma unroll
        for (int z = 0; z < 8; z++) {
            int m = m0 + ty + 16*z;
            out[(size_t)m*Dn + n] = hsum2(acc[z][w]) + bb;
        }
    }
}

// ---------------------------------------------------------------------------
// Flash attention v4: tf32 mma.sync (m16n8k8). Block = 128 q x 64 k tile,
// 256 threads = 8 warps, each warp owns a 16-row q strip (full 64-col width),
// so softmax row reductions stay within a 4-lane shfl group.
// Q/K/V/P staged in smem as tf32-rounded floats.
// ---------------------------------------------------------------------------
#define AQ 128
#define AK 64
#define SQ 68   // stride for Qs/Ks/Ps (A/B frag loads -> bank == laneID)
#define SV 72   // stride for Vs       (B frag loads -> bank == laneID)

__global__ __launch_bounds__(256) void attn_kernel()
{
    extern __shared__ float sm[];
    float* Qs = sm;               // [128][68] tf32
    float* Ks = Qs + AQ*SQ;       // [64][68]  tf32
    float* Ps = Ks + AK*SQ;       // [128][68] tf32
    float* Vs = Ps + AQ*SQ;       // [64][72]  tf32
    float* mS = Vs + AK*SV;       // [128]
    float* lS = mS + AQ;          // [128]
    float* cS = lS + AQ;          // [128]

    const int tid  = threadIdx.x;
    const int lane = tid & 31, wid = tid >> 5;
    const int gp = lane >> 2, tg = lane & 3;   // groupID, threadInGroup
    const int qw = wid * 16;                   // warp q-strip base
    const int bh = blockIdx.y;
    const int q0 = blockIdx.x * AQ;

    // ---- load Q (128x64), scale by 1/8, round to tf32 ----
    const float* Qp = g_Q + ((size_t)bh*Tn + q0)*DHn;
    for (int i = tid; i < AQ*16; i += 256) {
        int q = i >> 4, c = i & 15;
        float4 v = ((const float4*)Qp)[i];
        v.x = tf32r(v.x*0.125f); v.y = tf32r(v.y*0.125f);
        v.z = tf32r(v.z*0.125f); v.w = tf32r(v.w*0.125f);
        *(float4*)(Qs + q*SQ + 4*c) = v;
    }
    if (tid < AQ) { mS[tid] = -1e30f; lS[tid] = 0.0f; }

    const int r0 = qw + gp;        // this thread's first q row
    const int r1 = qw + gp + 8;    // second q row

    float o[8][4] = {};            // O accumulators: 8 d-tiles x (r0c0,r0c1,r1c0,r1c1)

    for (int j0 = 0; j0 < Tn; j0 += AK) {
        __syncthreads();  // prior PV reads of Ks/Vs done; Q/state init done

        // ---- load K, V (64x64 each), round to tf32 ----
        const float* Kp = g_K + ((size_t)bh*Tn + j0)*DHn;
        const float* Vp = g_V + ((size_t)bh*Tn + j0)*DHn;
        for (int i = tid; i < AK*16; i += 256) {
            int r = i >> 4, c = i & 15;
            float4 kv = ((const float4*)Kp)[i];
            kv.x = tf32r(kv.x); kv.y = tf32r(kv.y); kv.z = tf32r(kv.z); kv.w = tf32r(kv.w);
            *(float4*)(Ks + r*SQ + 4*c) = kv;
            float4 vv = ((const float4*)Vp)[i];
            vv.x = tf32r(vv.x); vv.y = tf32r(vv.y); vv.z = tf32r(vv.z); vv.w = tf32r(vv.w);
            *(float4*)(Vs + r*SV + 4*c) = vv;
        }
        __syncthreads();

        // ---- S = Q K^T : 8 n-tiles x m16n8, contract over DH=64 in k8 steps ----
        float s[8][4] = {};
        #pragma unroll
        for (int kk = 0; kk < 8; kk++) {
            unsigned a0 = fbits(Qs[r0*SQ + kk*8 + tg]);
            unsigned a1 = fbits(Qs[r1*SQ + kk*8 + tg]);
            unsigned a2 = fbits(Qs[r0*SQ + kk*8 + tg + 4]);
            unsigned a3 = fbits(Qs[r1*SQ + kk*8 + tg + 4]);
            #pragma unroll
            for (int nt = 0; nt < 8; nt++) {
                unsigned b0 = fbits(Ks[(nt*8+gp)*SQ + kk*8 + tg]);
                unsigned b1 = fbits(Ks[(nt*8+gp)*SQ + kk*8 + tg + 4]);
                mma_tf32(s[nt], a0, a1, a2, a3, b0, b1);
            }
        }

        // ---- mask + row max (rows r0, r1; cols 2tg,2tg+1 per n-tile) ----
        const uchar* m0p = g_mask + (size_t)(q0 + r0)*Tn + j0;
        const uchar* m1p = m0p + (size_t)8*Tn;
        float mx0 = -1e30f, mx1 = -1e30f;
        #pragma unroll
        for (int nt = 0; nt < 8; nt++) {
            int col = nt*8 + 2*tg;
            uchar mA0 = m0p[col], mA1 = m0p[col+1];
            uchar mB0 = m1p[col], mB1 = m1p[col+1];
            if (!mA0) s[nt][0] -= 1e9f;
            if (!mA1) s[nt][1] -= 1e9f;
            if (!mB0) s[nt][2] -= 1e9f;
            if (!mB1) s[nt][3] -= 1e9f;
            mx0 = fmaxf(mx0, fmaxf(s[nt][0], s[nt][1]));
            mx1 = fmaxf(mx1, fmaxf(s[nt][2], s[nt][3]));
        }
        mx0 = fmaxf(mx0, __shfl_xor_sync(0xffffffffu, mx0, 1));
        mx0 = fmaxf(mx0, __shfl_xor_sync(0xffffffffu, mx0, 2));
        mx1 = fmaxf(mx1, __shfl_xor_sync(0xffffffffu, mx1, 1));
        mx1 = fmaxf(mx1, __shfl_xor_sync(0xffffffffu, mx1, 2));

        float mo0 = mS[r0], mo1 = mS[r1];
        float mn0 = fmaxf(mo0, mx0), mn1 = fmaxf(mo1, mx1);

        // ---- exp, write P (tf32), accumulate partial row sums ----
        float l0 = 0.0f, l1 = 0.0f;
        #pragma unroll
        for (int nt = 0; nt < 8; nt++) {
            float p00 = __expf(s[nt][0] - mn0);
            float p01 = __expf(s[nt][1] - mn0);
            float p10 = __expf(s[nt][2] - mn1);
            float p11 = __expf(s[nt][3] - mn1);
            l0 += p00 + p01;
            l1 += p10 + p11;
            int col = nt*8 + 2*tg;
            *(float2*)(Ps + r0*SQ + col) = make_float2(tf32r(p00), tf32r(p01));
            *(float2*)(Ps + r1*SQ + col) = make_float2(tf32r(p10), tf32r(p11));
        }
        l0 += __shfl_xor_sync(0xffffffffu, l0, 1);
        l0 += __shfl_xor_sync(0xffffffffu, l0, 2);
        l1 += __shfl_xor_sync(0xffffffffu, l1, 1);
        l1 += __shfl_xor_sync(0xffffffffu, l1, 2);

        if (tg == 0) {
            float c0 = __expf(mo0 - mn0);
            float c1 = __expf(mo1 - mn1);
            mS[r0] = mn0; mS[r1] = mn1;
            cS[r0] = c0;  cS[r1] = c1;
            lS[r0] = lS[r0]*c0 + l0;
            lS[r1] = lS[r1]*c1 + l1;
        }
        __syncwarp();   // Ps rows + cS of this strip visible warp-wide

        // ---- O = O*corr + P V ----
        float c0 = cS[r0], c1 = cS[r1];
        #pragma unroll
        for (int nt = 0; nt < 8; nt++) {
            o[nt][0] *= c0; o[nt][1] *= c0;
            o[nt][2] *= c1; o[nt][3] *= c1;
        }
        #pragma unroll
        for (int kk = 0; kk < 8; kk++) {    // key chunks of 8
            unsigned a0 = fbits(Ps[r0*SQ + kk*8 + tg]);
            unsigned a1 = fbits(Ps[r1*SQ + kk*8 + tg]);
            unsigned a2 = fbits(Ps[r0*SQ + kk*8 + tg + 4]);
            unsigned a3 = fbits(Ps[r1*SQ + kk*8 + tg + 4]);
            #pragma unroll
            for (int nt = 0; nt < 8; nt++) {
                unsigned b0 = fbits(Vs[(kk*8+tg)*SV + nt*8 + gp]);
                unsigned b1 = fbits(Vs[(kk*8+tg+4)*SV + nt*8 + gp]);
                mma_tf32(o[nt], a0, a1, a2, a3, b0, b1);
            }
        }
    }

    // ---- finalize: normalize, write head-interleaved [b][t][d] ----
    const int b = bh >> 3, h = bh & 7;
    float inv0 = 1.0f / lS[r0];
    float inv1 = 1.0f / lS[r1];
    float* O0 = g_AO + ((size_t)(b*Tn + q0 + r0))*Dn + h*DHn;
    float* O1 = g_AO + ((size_t)(b*Tn + q0 + r1))*Dn + h*DHn;
    #pragma unroll
    for (int nt = 0; nt < 8; nt++) {
        int col = nt*8 + 2*tg;
        *(float2*)(O0 + col) = make_float2(o[nt][0]*inv0, o[nt][1]*inv0);
        *(float2*)(O1 + col) = make_float2(o[nt][2]*inv1, o[nt][3]*inv1);
    }
}

// ---------------------------------------------------------------------------
extern "C" void kernel_launch(void* const* d_in, const int* in_sizes, int n_in,
                              void* d_out, int out_size)
{
    const float* x  = (const float*)d_in[0];
    const float* Wq = (const float*)d_in[1];
    const float* bq = (const float*)d_in[2];
    const float* Wk = (const float*)d_in[3];
    const float* bk = (const float*)d_in[4];
    const float* Wv = (const float*)d_in[5];
    const float* bv = (const float*)d_in[6];
    const float* Wo = (const float*)d_in[7];
    const float* bo = (const float*)d_in[8];
    const void*  mask = (const void*)d_in[9];
    float* out = (float*)d_out;

    // smem: (128+64+128)*68 + 64*72 + 3*128 floats = 107,008 B -> 2 blocks/SM
    const int attn_smem = ((AQ + AK + AQ)*SQ + AK*SV + 3*AQ) * 4;
    cudaFuncSetAttribute(attn_kernel, cudaFuncAttributeMaxDynamicSharedMemorySize, attn_smem);

    detect_mask<<<1, 32>>>(mask);
    convert_mask<<<1024, 256>>>(mask);
    qkv_gemm<<<dim3(Dn/64, (Bn*Tn)/128, 3), 256>>>(x, Wq, Wk, Wv, bq, bk, bv);
    attn_kernel<<<dim3(Tn/AQ, BHn), 256, attn_smem>>>();
    out_gemm<<<dim3(Dn/64, (Bn*Tn)/128), 256>>>(Wo, bo, out);
}

// round 9
// speedup vs baseline: 2.2039x; 1.1250x over previous
#include <cuda_runtime.h>

// Problem constants
#define Bn  2
#define Tn  4096
#define Dn  512
#define Hn  8
#define DHn 64
#define BHn (Bn*Hn)

typedef unsigned long long u64;
typedef unsigned char uchar;

// Scratch (device globals: no allocation allowed)
__device__ float g_Q [BHn*Tn*DHn];   // [bh][t][dh]
__device__ float g_K [BHn*Tn*DHn];
__device__ float g_V [BHn*Tn*DHn];
__device__ float g_AO[Bn*Tn*Dn];     // [b][t][d]  attention output, pre-Wo
__device__ unsigned g_mbits[(size_t)Tn*Tn/32];  // bit-packed mask
__device__ int g_mask_mode;                     // 0=uint8, 1=int32, 2=float32

// ---- packed f32x2 helpers (GEMMs) ----------------------------------------
__device__ __forceinline__ u64 pk2(float lo, float hi) {
    u64 d; asm("mov.b64 %0, {%1, %2};" : "=l"(d) : "f"(lo), "f"(hi)); return d;
}
__device__ __forceinline__ void upk2(float& lo, float& hi, u64 v) {
    asm("mov.b64 {%0, %1}, %2;" : "=f"(lo), "=f"(hi) : "l"(v));
}
__device__ __forceinline__ u64 fma2(u64 a, u64 b, u64 c) {
    u64 d; asm("fma.rn.f32x2 %0, %1, %2, %3;" : "=l"(d) : "l"(a), "l"(b), "l"(c)); return d;
}
__device__ __forceinline__ float hsum2(u64 v) {
    float lo, hi; upk2(lo, hi, v); return lo + hi;
}

// ---- tf32 / mma / ldmatrix helpers ----------------------------------------
__device__ __forceinline__ float tf32r(float x) {
    float r; asm("cvt.rna.tf32.f32 %0, %1;" : "=f"(r) : "f"(x)); return r;
}
__device__ __forceinline__ void mma_tf32(float c[4],
    unsigned a0, unsigned a1, unsigned a2, unsigned a3, unsigned b0, unsigned b1)
{
    asm volatile(
        "mma.sync.aligned.m16n8k8.row.col.f32.tf32.tf32.f32 "
        "{%0,%1,%2,%3}, {%4,%5,%6,%7}, {%8,%9}, {%0,%1,%2,%3};"
        : "+f"(c[0]), "+f"(c[1]), "+f"(c[2]), "+f"(c[3])
        : "r"(a0), "r"(a1), "r"(a2), "r"(a3), "r"(b0), "r"(b1));
}
__device__ __forceinline__ void ldsm4(unsigned &d0, unsigned &d1, unsigned &d2, unsigned &d3,
                                      unsigned addr)
{
    asm volatile("ldmatrix.sync.aligned.m8n8.x4.shared.b16 {%0,%1,%2,%3}, [%4];"
        : "=r"(d0), "=r"(d1), "=r"(d2), "=r"(d3) : "r"(addr));
}
__device__ __forceinline__ unsigned sm_u32(const void* p) {
    return (unsigned)__cvta_generic_to_shared(p);
}

// ---------------------------------------------------------------------------
// Mask dtype sniffing + bit-pack (bool arrives as int32).
// ---------------------------------------------------------------------------
__global__ void detect_mask(const void* __restrict__ mask)
{
    if (threadIdx.x != 0 || blockIdx.x != 0) return;
    const unsigned* w = (const unsigned*)mask;
    bool is_i32 = true, is_f32 = true;
    for (int i = 0; i < 1024; i++) {
        unsigned v = w[i];
        if (v != 0u && v != 1u)           is_i32 = false;
        if (v != 0u && v != 0x3F800000u)  is_f32 = false;
    }
    g_mask_mode = is_i32 ? 1 : (is_f32 ? 2 : 0);
}

__global__ __launch_bounds__(256) void convert_mask(const void* __restrict__ mask)
{
    const int mode = g_mask_mode;
    const int nw = Tn*Tn/32;
    int i = blockIdx.x*blockDim.x + threadIdx.x;
    int stride = gridDim.x*blockDim.x;
    if (mode == 1) {
        const int4* m = (const int4*)mask;
        for (; i < nw; i += stride) {
            unsigned w = 0;
            #pragma unroll
            for (int j = 0; j < 8; j++) {
                int4 v = m[(size_t)i*8 + j];
                w |= (v.x != 0 ? 1u : 0u) << (4*j);
                w |= (v.y != 0 ? 1u : 0u) << (4*j+1);
                w |= (v.z != 0 ? 1u : 0u) << (4*j+2);
                w |= (v.w != 0 ? 1u : 0u) << (4*j+3);
            }
            g_mbits[i] = w;
        }
    } else if (mode == 2) {
        const float4* m = (const float4*)mask;
        for (; i < nw; i += stride) {
            unsigned w = 0;
            #pragma unroll
            for (int j = 0; j < 8; j++) {
                float4 v = m[(size_t)i*8 + j];
                w |= (v.x != 0.0f ? 1u : 0u) << (4*j);
                w |= (v.y != 0.0f ? 1u : 0u) << (4*j+1);
                w |= (v.z != 0.0f ? 1u : 0u) << (4*j+2);
                w |= (v.w != 0.0f ? 1u : 0u) << (4*j+3);
            }
            g_mbits[i] = w;
        }
    } else {
        const uchar* m = (const uchar*)mask;
        for (; i < nw; i += stride) {
            unsigned w = 0;
            #pragma unroll
            for (int j = 0; j < 32; j++)
                w |= (m[(size_t)i*32 + j] != 0 ? 1u : 0u) << j;
            g_mbits[i] = w;
        }
    }
}

// ---------------------------------------------------------------------------
// SGEMM with f32x2 (known correct): C(128x64)/block, BK=16, 256 threads.
// ---------------------------------------------------------------------------
#define GS_A (128*18)
#define GS_B (64*18)

__device__ __forceinline__ void gemm_core(
    const float* __restrict__ X, const float* __restrict__ W,
    float* As, float* Bt, int m0, int n0, u64 acc[8][4])
{
    const int tid = threadIdx.x;
    const int lb_k = tid >> 4, lb_n4 = tid & 15;

    for (int k0 = 0; k0 < Dn; k0 += 16) {
        float4 av[2];
        #pragma unroll
        for (int r = 0; r < 2; r++) {
            int i = tid + 256*r;
            int m = i >> 2, c = i & 3;
            av[r] = ((const float4*)X)[(size_t)(m0+m)*(Dn/4) + (k0>>2) + c];
        }
        float4 bv4 = ((const float4*)W)[(size_t)(k0+lb_k)*(Dn/4) + (n0>>2) + lb_n4];
        __syncthreads();
        #pragma unroll
        for (int r = 0; r < 2; r++) {
            int i = tid + 256*r;
            int m = i >> 2, c = i & 3;
            *(u64*)(As + m*18 + 4*c)     = pk2(av[r].x, av[r].y);
            *(u64*)(As + m*18 + 4*c + 2) = pk2(av[r].z, av[r].w);
        }
        Bt[(4*lb_n4+0)*18 + lb_k] = bv4.x;
        Bt[(4*lb_n4+1)*18 + lb_k] = bv4.y;
        Bt[(4*lb_n4+2)*18 + lb_k] = bv4.z;
        Bt[(4*lb_n4+3)*18 + lb_k] = bv4.w;
        __syncthreads();

        const int tx = tid & 15, ty = tid >> 4;
        #pragma unroll
        for (int k2 = 0; k2 < 8; k2++) {
            u64 a[8], b[4];
            #pragma unroll
            for (int z = 0; z < 8; z++) a[z] = *(const u64*)(As + (ty+16*z)*18 + 2*k2);
            #pragma unroll
            for (int w = 0; w < 4; w++) b[w] = *(const u64*)(Bt + (tx+16*w)*18 + 2*k2);
            #pragma unroll
            for (int z = 0; z < 8; z++)
                #pragma unroll
                for (int w = 0; w < 4; w++)
                    acc[z][w] = fma2(a[z], b[w], acc[z][w]);
        }
    }
}

__global__ __launch_bounds__(256) void qkv_gemm(
    const float* __restrict__ X,
    const float* __restrict__ Wq, const float* __restrict__ Wk, const float* __restrict__ Wv,
    const float* __restrict__ bq, const float* __restrict__ bk, const float* __restrict__ bv)
{
    const float* W; const float* bias; float* out;
    if      (blockIdx.z == 0) { W = Wq; bias = bq; out = g_Q; }
    else if (blockIdx.z == 1) { W = Wk; bias = bk; out = g_K; }
    else                      { W = Wv; bias = bv; out = g_V; }

    __shared__ float As[GS_A];
    __shared__ float Bt[GS_B];

    const int tid = threadIdx.x;
    const int tx = tid & 15, ty = tid >> 4;
    const int m0 = blockIdx.y * 128, n0 = blockIdx.x * 64;

    u64 acc[8][4] = {};
    gemm_core(X, W, As, Bt, m0, n0, acc);

    const int h = n0 / DHn;
    #pragma unroll
    for (int w = 0; w < 4; w++) {
        int dh = tx + 16*w;
        float bb = bias[n0 + dh];
        #pragma unroll
        for (int z = 0; z < 8; z++) {
            int m = m0 + ty + 16*z;
            int b = m / Tn, t = m % Tn;
            out[((size_t)((b*Hn + h)*Tn + t))*DHn + dh] = hsum2(acc[z][w]) + bb;
        }
    }
}

__global__ __launch_bounds__(256) void out_gemm(
    const float* __restrict__ W, const float* __restrict__ bias, float* __restrict__ out)
{
    __shared__ float As[GS_A];
    __shared__ float Bt[GS_B];

    const int tid = threadIdx.x;
    const int tx = tid & 15, ty = tid >> 4;
    const int m0 = blockIdx.y * 128, n0 = blockIdx.x * 64;

    u64 acc[8][4] = {};
    gemm_core(g_AO, W, As, Bt, m0, n0, acc);

    #pragma unroll
    for (int w = 0; w < 4; w++) {
        int n = n0 + tx + 16*w;
        float bb = bias[n];
        #pragma unroll
        for (int z = 0; z < 8; z++) {
            int m = m0 + ty + 16*z;
            out[(size_t)m*Dn + n] = hsum2(acc[z][w]) + bb;
        }
    }
}

// ---------------------------------------------------------------------------
// Flash attention v5: tf32 mma.sync + ldmatrix fragment loads.
// Block = 128 q x 64 k tile, 8 warps, warp owns a 16-row q strip.
// Qs/Ks/Ps padded stride 68 (conflict-free LDSM); Vt transposed + XOR-swizzled.
// Mask read from bit-packed g_mbits.
// ---------------------------------------------------------------------------
#define AQ 128
#define AK 64
#define SQ 68

__global__ __launch_bounds__(256) void attn_kernel()
{
    extern __shared__ float sm[];
    float* Qs = sm;               // [128][68] tf32
    float* Ks = Qs + AQ*SQ;       // [64][68]  tf32
    float* Ps = Ks + AK*SQ;       // [128][68] tf32
    float* Vt = Ps + AQ*SQ;       // [64][64]  tf32, transposed + swizzled
    float* mS = Vt + 64*64;       // [128]
    float* lS = mS + AQ;          // [128]
    float* cS = lS + AQ;          // [128]

    const int tid  = threadIdx.x;
    const int lane = tid & 31, wid = tid >> 5;
    const int gp = lane >> 2, tg = lane & 3;
    const int qw = wid * 16;
    const int bh = blockIdx.y;
    const int q0 = blockIdx.x * AQ;

    // ldmatrix per-lane bases
    const int lr = lane & 7, sub = lane >> 3;
    const int c01 = sub & 1;
    const int arow = qw + lr + c01*8;          // A-pattern: m0/m2 rows qw.., m1/m3 rows qw+8..
    const int acol = (sub >> 1) * 4;
    const unsigned aQb = sm_u32(Qs + arow*SQ + acol);
    const unsigned aPb = sm_u32(Ps + arow*SQ + acol);
    unsigned bKb[4], bVb[4];
    int eV[4];
    #pragma unroll
    for (int p = 0; p < 4; p++) {              // nt pair (2p, 2p+1)
        int brow = (2*p + (sub >> 1))*8 + lr;  // m0/m1 rows nt*8.., m2/m3 rows (nt+1)*8..
        bKb[p] = sm_u32(Ks + brow*SQ + c01*4);
        bVb[p] = sm_u32(Vt + brow*64);
        eV[p]  = brow & 7;
    }

    // ---- load Q (128x64), scale 1/8, tf32 round ----
    const float* Qp = g_Q + ((size_t)bh*Tn + q0)*DHn;
    for (int i = tid; i < AQ*16; i += 256) {
        int q = i >> 4, c = i & 15;
        float4 v = ((const float4*)Qp)[i];
        v.x = tf32r(v.x*0.125f); v.y = tf32r(v.y*0.125f);
        v.z = tf32r(v.z*0.125f); v.w = tf32r(v.w*0.125f);
        *(float4*)(Qs + q*SQ + 4*c) = v;
    }
    if (tid < AQ) { mS[tid] = -1e30f; lS[tid] = 0.0f; }

    const int r0 = qw + gp, r1 = r0 + 8;

    float o[8][4] = {};

    for (int j0 = 0; j0 < Tn; j0 += AK) {
        __syncthreads();  // prior PV reads of Ks/Vt done; Q/state init done

        const float* Kp = g_K + ((size_t)bh*Tn + j0)*DHn;
        const float* Vp = g_V + ((size_t)bh*Tn + j0)*DHn;
        // K natural rows, stride 68
        for (int i = tid; i < AK*16; i += 256) {
            int r = i >> 4, c = i & 15;
            float4 kv = ((const float4*)Kp)[i];
            kv.x = tf32r(kv.x); kv.y = tf32r(kv.y); kv.z = tf32r(kv.z); kv.w = tf32r(kv.w);
            *(float4*)(Ks + r*SQ + 4*c) = kv;
        }
        // V transposed + swizzled: lane->key mapping keeps STS conflict-free
        #pragma unroll
        for (int it = 0; it < 4; it++) {
            int n = (tid & 31) + 32*(it & 1);          // key
            int c = (tid >> 5) + 8*(it >> 1);          // dim group (4 floats)
            float4 vv = *(const float4*)(Vp + (size_t)n*DHn + 4*c);
            float e[4] = {tf32r(vv.x), tf32r(vv.y), tf32r(vv.z), tf32r(vv.w)};
            #pragma unroll
            for (int z = 0; z < 4; z++) {
                int d = 4*c + z;
                Vt[d*64 + 4*((n >> 2) ^ (d & 7)) + (n & 3)] = e[z];
            }
        }
        __syncthreads();

        // ---- S = Q K^T : ldmatrix + mma ----
        float s[8][4] = {};
        #pragma unroll
        for (int kk = 0; kk < 8; kk++) {
            unsigned a0, a1, a2, a3;
            ldsm4(a0, a1, a2, a3, aQb + kk*32);
            #pragma unroll
            for (int p = 0; p < 4; p++) {
                unsigned b0, b1, b2, b3;
                ldsm4(b0, b1, b2, b3, bKb[p] + kk*32);
                mma_tf32(s[2*p],   a0, a1, a2, a3, b0, b1);
                mma_tf32(s[2*p+1], a0, a1, a2, a3, b2, b3);
            }
        }

        // ---- mask (bit-packed) + row max ----
        const unsigned* Mb0 = g_mbits + (size_t)(q0 + r0)*(Tn/32) + (j0 >> 5);
        const unsigned* Mb1 = Mb0 + (size_t)8*(Tn/32);
        unsigned w0a = Mb0[0], w0b = Mb0[1];
        unsigned w1a = Mb1[0], w1b = Mb1[1];
        float mx0 = -1e30f, mx1 = -1e30f;
        #pragma unroll
        for (int nt = 0; nt < 8; nt++) {
            unsigned wr0 = (nt < 4) ? w0a : w0b;
            unsigned wr1 = (nt < 4) ? w1a : w1b;
            int sh = (nt & 3)*8 + 2*tg;
            if (!((wr0 >> sh) & 1))       s[nt][0] -= 1e9f;
            if (!((wr0 >> (sh+1)) & 1))   s[nt][1] -= 1e9f;
            if (!((wr1 >> sh) & 1))       s[nt][2] -= 1e9f;
            if (!((wr1 >> (sh+1)) & 1))   s[nt][3] -= 1e9f;
            mx0 = fmaxf(mx0, fmaxf(s[nt][0], s[nt][1]));
            mx1 = fmaxf(mx1, fmaxf(s[nt][2], s[nt][3]));
        }
        mx0 = fmaxf(mx0, __shfl_xor_sync(0xffffffffu, mx0, 1));
        mx0 = fmaxf(mx0, __shfl_xor_sync(0xffffffffu, mx0, 2));
        mx1 = fmaxf(mx1, __shfl_xor_sync(0xffffffffu, mx1, 1));
        mx1 = fmaxf(mx1, __shfl_xor_sync(0xffffffffu, mx1, 2));

        float mo0 = mS[r0], mo1 = mS[r1];
        float mn0 = fmaxf(mo0, mx0), mn1 = fmaxf(mo1, mx1);

        // ---- exp, write P (tf32), partial row sums ----
        float l0 = 0.0f, l1 = 0.0f;
        #pragma unroll
        for (int nt = 0; nt < 8; nt++) {
            float p00 = __expf(s[nt][0] - mn0);
            float p01 = __expf(s[nt][1] - mn0);
            float p10 = __expf(s[nt][2] - mn1);
            float p11 = __expf(s[nt][3] - mn1);
            l0 += p00 + p01;
            l1 += p10 + p11;
            int col = nt*8 + 2*tg;
            *(float2*)(Ps + r0*SQ + col) = make_float2(tf32r(p00), tf32r(p01));
            *(float2*)(Ps + r1*SQ + col) = make_float2(tf32r(p10), tf32r(p11));
        }
        l0 += __shfl_xor_sync(0xffffffffu, l0, 1);
        l0 += __shfl_xor_sync(0xffffffffu, l0, 2);
        l1 += __shfl_xor_sync(0xffffffffu, l1, 1);
        l1 += __shfl_xor_sync(0xffffffffu, l1, 2);

        if (tg == 0) {
            float c0 = __expf(mo0 - mn0);
            float c1 = __expf(mo1 - mn1);
            mS[r0] = mn0; mS[r1] = mn1;
            cS[r0] = c0;  cS[r1] = c1;
            lS[r0] = lS[r0]*c0 + l0;
            lS[r1] = lS[r1]*c1 + l1;
        }
        __syncwarp();   // Ps strip + cS visible warp-wide

        // ---- O = O*corr + P V : ldmatrix + mma ----
        float c0 = cS[r0], c1 = cS[r1];
        #pragma unroll
        for (int nt = 0; nt < 8; nt++) {
            o[nt][0] *= c0; o[nt][1] *= c0;
            o[nt][2] *= c1; o[nt][3] *= c1;
        }
        #pragma unroll
        for (int kk = 0; kk < 8; kk++) {
            unsigned a0, a1, a2, a3;
            ldsm4(a0, a1, a2, a3, aPb + kk*32);
            #pragma unroll
            for (int p = 0; p < 4; p++) {
                unsigned b0, b1, b2, b3;
                unsigned ofs = (unsigned)(((2*kk + c01) ^ eV[p]) << 4);
                ldsm4(b0, b1, b2, b3, bVb[p] + ofs);
                mma_tf32(o[2*p],   a0, a1, a2, a3, b0, b1);
                mma_tf32(o[2*p+1], a0, a1, a2, a3, b2, b3);
            }
        }
    }

    // ---- finalize: normalize, write head-interleaved [b][t][d] ----
    const int b = bh >> 3, h = bh & 7;
    float inv0 = 1.0f / lS[r0];
    float inv1 = 1.0f / lS[r1];
    float* O0 = g_AO + ((size_t)(b*Tn + q0 + r0))*Dn + h*DHn;
    float* O1 = g_AO + ((size_t)(b*Tn + q0 + r1))*Dn + h*DHn;
    #pragma unroll
    for (int nt = 0; nt < 8; nt++) {
        int col = nt*8 + 2*tg;
        *(float2*)(O0 + col) = make_float2(o[nt][0]*inv0, o[nt][1]*inv0);
        *(float2*)(O1 + col) = make_float2(o[nt][2]*inv1, o[nt][3]*inv1);
    }
}

// ---------------------------------------------------------------------------
extern "C" void kernel_launch(void* const* d_in, const int* in_sizes, int n_in,
                              void* d_out, int out_size)
{
    const float* x  = (const float*)d_in[0];
    const float* Wq = (const float*)d_in[1];
    const float* bq = (const float*)d_in[2];
    const float* Wk = (const float*)d_in[3];
    const float* bk = (const float*)d_in[4];
    const float* Wv = (const float*)d_in[5];
    const float* bv = (const float*)d_in[6];
    const float* Wo = (const float*)d_in[7];
    const float* bo = (const float*)d_in[8];
    const void*  mask = (const void*)d_in[9];
    float* out = (float*)d_out;

    // smem: 320*68 + 64*64 + 3*128 floats = 104,960 B
    const int attn_smem = ((AQ + AK + AQ)*SQ + AK*64 + 3*AQ) * 4;
    cudaFuncSetAttribute(attn_kernel, cudaFuncAttributeMaxDynamicSharedMemorySize, attn_smem);

    detect_mask<<<1, 32>>>(mask);
    convert_mask<<<2048, 256>>>(mask);
    qkv_gemm<<<dim3(Dn/64, (Bn*Tn)/128, 3), 256>>>(x, Wq, Wk, Wv, bq, bk, bv);
    attn_kernel<<<dim3(Tn/AQ, BHn), 256, attn_smem>>>();
    out_gemm<<<dim3(Dn/64, (Bn*Tn)/128), 256>>>(Wo, bo, out);
}

// round 12
// speedup vs baseline: 2.8360x; 1.2868x over previous
#include <cuda_runtime.h>

// Problem constants
#define Bn  2
#define Tn  4096
#define Dn  512
#define Hn  8
#define DHn 64
#define BHn (Bn*Hn)

typedef unsigned char uchar;

// Scratch (device globals: no allocation allowed)
__device__ float g_Q [BHn*Tn*DHn];   // [bh][t][dh]
__device__ float g_K [BHn*Tn*DHn];
__device__ float g_V [BHn*Tn*DHn];
__device__ float g_AO[Bn*Tn*Dn];     // [b][t][d]  attention output, pre-Wo
__device__ unsigned g_mbits[(size_t)Tn*Tn/32];  // bit-packed mask
__device__ int g_mask_mode;                     // 0=uint8, 1=int32, 2=float32

// ---- tf32 / mma / ldmatrix helpers ----------------------------------------
__device__ __forceinline__ float tf32r(float x) {
    float r; asm("cvt.rna.tf32.f32 %0, %1;" : "=f"(r) : "f"(x)); return r;
}
__device__ __forceinline__ void mma_tf32(float c[4],
    unsigned a0, unsigned a1, unsigned a2, unsigned a3, unsigned b0, unsigned b1)
{
    asm volatile(
        "mma.sync.aligned.m16n8k8.row.col.f32.tf32.tf32.f32 "
        "{%0,%1,%2,%3}, {%4,%5,%6,%7}, {%8,%9}, {%0,%1,%2,%3};"
        : "+f"(c[0]), "+f"(c[1]), "+f"(c[2]), "+f"(c[3])
        : "r"(a0), "r"(a1), "r"(a2), "r"(a3), "r"(b0), "r"(b1));
}
__device__ __forceinline__ void ldsm4(unsigned &d0, unsigned &d1, unsigned &d2, unsigned &d3,
                                      unsigned addr)
{
    asm volatile("ldmatrix.sync.aligned.m8n8.x4.shared.b16 {%0,%1,%2,%3}, [%4];"
        : "=r"(d0), "=r"(d1), "=r"(d2), "=r"(d3) : "r"(addr));
}
__device__ __forceinline__ unsigned sm_u32(const void* p) {
    return (unsigned)__cvta_generic_to_shared(p);
}
__device__ __forceinline__ unsigned fbits(float x) { return __float_as_uint(x); }

// ---------------------------------------------------------------------------
// Mask dtype sniffing + bit-pack (bool arrives as int32).
// ---------------------------------------------------------------------------
__global__ void detect_mask(const void* __restrict__ mask)
{
    if (threadIdx.x != 0 || blockIdx.x != 0) return;
    const unsigned* w = (const unsigned*)mask;
    bool is_i32 = true, is_f32 = true;
    for (int i = 0; i < 1024; i++) {
        unsigned v = w[i];
        if (v != 0u && v != 1u)           is_i32 = false;
        if (v != 0u && v != 0x3F800000u)  is_f32 = false;
    }
    g_mask_mode = is_i32 ? 1 : (is_f32 ? 2 : 0);
}

__global__ __launch_bounds__(256) void convert_mask(const void* __restrict__ mask)
{
    const int mode = g_mask_mode;
    const int nw = Tn*Tn/32;
    int i = blockIdx.x*blockDim.x + threadIdx.x;
    int stride = gridDim.x*blockDim.x;
    if (mode == 1) {
        const int4* m = (const int4*)mask;
        for (; i < nw; i += stride) {
            unsigned w = 0;
            #pragma unroll
            for (int j = 0; j < 8; j++) {
                int4 v = m[(size_t)i*8 + j];
                w |= (v.x != 0 ? 1u : 0u) << (4*j);
                w |= (v.y != 0 ? 1u : 0u) << (4*j+1);
                w |= (v.z != 0 ? 1u : 0u) << (4*j+2);
                w |= (v.w != 0 ? 1u : 0u) << (4*j+3);
            }
            g_mbits[i] = w;
        }
    } else if (mode == 2) {
        const float4* m = (const float4*)mask;
        for (; i < nw; i += stride) {
            unsigned w = 0;
            #pragma unroll
            for (int j = 0; j < 8; j++) {
                float4 v = m[(size_t)i*8 + j];
                w |= (v.x != 0.0f ? 1u : 0u) << (4*j);
                w |= (v.y != 0.0f ? 1u : 0u) << (4*j+1);
                w |= (v.z != 0.0f ? 1u : 0u) << (4*j+2);
                w |= (v.w != 0.0f ? 1u : 0u) << (4*j+3);
            }
            g_mbits[i] = w;
        }
    } else {
        const uchar* m = (const uchar*)mask;
        for (; i < nw; i += stride) {
            unsigned w = 0;
            #pragma unroll
            for (int j = 0; j < 32; j++)
                w |= (m[(size_t)i*32 + j] != 0 ? 1u : 0u) << j;
            g_mbits[i] = w;
        }
    }
}

// ---------------------------------------------------------------------------
// tf32 MMA projection GEMM core. C tile 128x64, 256 threads, 8 warps each
// owning a 16-row strip (8 n-tiles of m16n8). K-loop BK=64.
// Xs: natural rows, stride 68 (conflict-free LDSM). Bt: W^T [n][k] with the
// XOR-16B swizzle validated by the attention V path.
// ---------------------------------------------------------------------------
__device__ __forceinline__ void mma_gemm_core(
    const float* __restrict__ X, const float* __restrict__ W,
    float* Xs, float* Bt, int m0, int n0, float acc[8][4])
{
    const int tid = threadIdx.x;
    const int lane = tid & 31, wid = tid >> 5;
    const int lr = lane & 7, sub = lane >> 3, c01 = sub & 1;
    const int qw = wid * 16;
    const unsigned aXb = sm_u32(Xs + (qw + lr + c01*8)*68 + (sub>>1)*4);
    unsigned bWb[4]; int eW[4];
    #pragma unroll
    for (int p = 0; p < 4; p++) {
        int brow = (2*p + (sub>>1))*8 + lr;
        bWb[p] = sm_u32(Bt + brow*64);
        eW[p]  = brow & 7;
    }

    for (int k0 = 0; k0 < Dn; k0 += 64) {
        // LDG: X tile 128x64 (coalesced), W strip 64x64 (k-major, L2-hot)
        float4 xv[8];
        #pragma unroll
        for (int r = 0; r < 8; r++) {
            int i = tid + 256*r;
            int rr = i >> 4, c = i & 15;
            xv[r] = ((const float4*)X)[(size_t)(m0+rr)*(Dn/4) + (k0>>2) + c];
        }
        float4 wv[4];
        #pragma unroll
        for (int it = 0; it < 4; it++) {
            int k = (tid & 31) + 32*(it & 1);
            int c = (tid >> 5) + 8*(it >> 1);
            wv[it] = *(const float4*)(W + (size_t)(k0+k)*Dn + n0 + 4*c);
        }
        __syncthreads();   // prior MMA reads done
        #pragma unroll
        for (int r = 0; r < 8; r++) {
            int i = tid + 256*r;
            int rr = i >> 4, c = i & 15;
            float4 v = xv[r];
            v.x = tf32r(v.x); v.y = tf32r(v.y); v.z = tf32r(v.z); v.w = tf32r(v.w);
            *(float4*)(Xs + rr*68 + 4*c) = v;
        }
        #pragma unroll
        for (int it = 0; it < 4; it++) {
            int k = (tid & 31) + 32*(it & 1);
            int c = (tid >> 5) + 8*(it >> 1);
            float e[4] = {tf32r(wv[it].x), tf32r(wv[it].y), tf32r(wv[it].z), tf32r(wv[it].w)};
            #pragma unroll
            for (int z = 0; z < 4; z++) {
                int n = 4*c + z;
                Bt[n*64 + 4*((k>>2)^(n&7)) + (k&3)] = e[z];
            }
        }
        __syncthreads();
        #pragma unroll
        for (int kk = 0; kk < 8; kk++) {
            unsigned a0,a1,a2,a3;
            ldsm4(a0,a1,a2,a3, aXb + kk*32);
            #pragma unroll
            for (int p = 0; p < 4; p++) {
                unsigned b0,b1,b2,b3;
                unsigned ofs = (unsigned)(((2*kk + c01) ^ eW[p]) << 4);
                ldsm4(b0,b1,b2,b3, bWb[p] + ofs);
                mma_tf32(acc[2*p],   a0,a1,a2,a3, b0,b1);
                mma_tf32(acc[2*p+1], a0,a1,a2,a3, b2,b3);
            }
        }
    }
}

#define GEMM_SMEM ((128*68 + 64*64) * 4)

__global__ __launch_bounds__(256) void qkv_gemm(
    const float* __restrict__ X,
    const float* __restrict__ Wq, const float* __restrict__ Wk, const float* __restrict__ Wv,
    const float* __restrict__ bq, const float* __restrict__ bk, const float* __restrict__ bv)
{
    extern __shared__ float smg[];
    float* Xs = smg;              // [128][68]
    float* Bt = smg + 128*68;     // [64][64] swizzled W^T

    const float* W; const float* bias; float* out;
    if      (blockIdx.z == 0) { W = Wq; bias = bq; out = g_Q; }
    else if (blockIdx.z == 1) { W = Wk; bias = bk; out = g_K; }
    else                      { W = Wv; bias = bv; out = g_V; }

    const int m0 = blockIdx.y * 128, n0 = blockIdx.x * 64;
    float acc[8][4] = {};
    mma_gemm_core(X, W, Xs, Bt, m0, n0, acc);

    const int lane = threadIdx.x & 31, wid = threadIdx.x >> 5;
    const int gp = lane >> 2, tg = lane & 3;
    const int h = blockIdx.x;     // 64-wide n tile = one head
    const int m_a = m0 + wid*16 + gp, m_b = m_a + 8;
    const int ba = m_a >> 12, ta = m_a & (Tn-1);
    const int bb = m_b >> 12, tb = m_b & (Tn-1);
    float* oa = out + ((size_t)((ba*Hn + h)*Tn + ta))*DHn;
    float* ob = out + ((size_t)((bb*Hn + h)*Tn + tb))*DHn;
    #pragma unroll
    for (int nt = 0; nt < 8; nt++) {
        int dh = nt*8 + 2*tg;
        float bx = bias[n0 + dh], by = bias[n0 + dh + 1];
        *(float2*)(oa + dh) = make_float2(acc[nt][0]+bx, acc[nt][1]+by);
        *(float2*)(ob + dh) = make_float2(acc[nt][2]+bx, acc[nt][3]+by);
    }
}

__global__ __launch_bounds__(256) void out_gemm(
    const float* __restrict__ W, const float* __restrict__ bias, float* __restrict__ out)
{
    extern __shared__ float smg[];
    float* Xs = smg;
    float* Bt = smg + 128*68;

    const int m0 = blockIdx.y * 128, n0 = blockIdx.x * 64;
    float acc[8][4] = {};
    mma_gemm_core(g_AO, W, Xs, Bt, m0, n0, acc);

    const int lane = threadIdx.x & 31, wid = threadIdx.x >> 5;
    const int gp = lane >> 2, tg = lane & 3;
    const int m_a = m0 + wid*16 + gp, m_b = m_a + 8;
    #pragma unroll
    for (int nt = 0; nt < 8; nt++) {
        int n = n0 + nt*8 + 2*tg;
        float bx = bias[n], by = bias[n+1];
        *(float2*)(out + (size_t)m_a*Dn + n) = make_float2(acc[nt][0]+bx, acc[nt][1]+by);
        *(float2*)(out + (size_t)m_b*Dn + n) = make_float2(acc[nt][2]+bx, acc[nt][3]+by);
    }
}

// ---------------------------------------------------------------------------
// Flash attention v6: tf32 mma + ldmatrix; P kept in registers (C-frag ->
// A-frag via shfl exchange, no Ps smem roundtrip); softmax state in registers.
// Block = 128 q x 64 k tile, 8 warps, warp owns a 16-row q strip.
// ---------------------------------------------------------------------------
#define AQ 128
#define AK 64
#define SQ 68

__global__ __launch_bounds__(256) void attn_kernel()
{
    extern __shared__ float sm[];
    float* Qs = sm;               // [128][68] tf32
    float* Ks = Qs + AQ*SQ;       // [64][68]  tf32
    float* Vt = Ks + AK*SQ;       // [64][64]  tf32, transposed + swizzled

    const int tid  = threadIdx.x;
    const int lane = tid & 31, wid = tid >> 5;
    const int gp = lane >> 2, tg = lane & 3;
    const int qw = wid * 16;
    const int bh = blockIdx.y;
    const int q0 = blockIdx.x * AQ;

    const int lr = lane & 7, sub = lane >> 3, c01 = sub & 1;
    const unsigned aQb = sm_u32(Qs + (qw + lr + c01*8)*SQ + (sub>>1)*4);
    unsigned bKb[4], bVb[4];
    int eV[4];
    #pragma unroll
    for (int p = 0; p < 4; p++) {
        int brow = (2*p + (sub >> 1))*8 + lr;
        bKb[p] = sm_u32(Ks + brow*SQ + c01*4);
        bVb[p] = sm_u32(Vt + brow*64);
        eV[p]  = brow & 7;
    }

    // ---- load Q (128x64), scale 1/8, tf32 round ----
    const float* Qp = g_Q + ((size_t)bh*Tn + q0)*DHn;
    for (int i = tid; i < AQ*16; i += 256) {
        int q = i >> 4, c = i & 15;
        float4 v = ((const float4*)Qp)[i];
        v.x = tf32r(v.x*0.125f); v.y = tf32r(v.y*0.125f);
        v.z = tf32r(v.z*0.125f); v.w = tf32r(v.w*0.125f);
        *(float4*)(Qs + q*SQ + 4*c) = v;
    }

    const int r0 = qw + gp, r1 = r0 + 8;
    float m0r = -1e30f, m1r = -1e30f, l0r = 0.0f, l1r = 0.0f;
    float o[8][4] = {};

    for (int j0 = 0; j0 < Tn; j0 += AK) {
        __syncthreads();  // prior tile's Ks/Vt reads done (and Q init on iter 0)

        const float* Kp = g_K + ((size_t)bh*Tn + j0)*DHn;
        const float* Vp = g_V + ((size_t)bh*Tn + j0)*DHn;
        for (int i = tid; i < AK*16; i += 256) {
            int r = i >> 4, c = i & 15;
            float4 kv = ((const float4*)Kp)[i];
            kv.x = tf32r(kv.x); kv.y = tf32r(kv.y); kv.z = tf32r(kv.z); kv.w = tf32r(kv.w);
            *(float4*)(Ks + r*SQ + 4*c) = kv;
        }
        #pragma unroll
        for (int it = 0; it < 4; it++) {
            int n = (tid & 31) + 32*(it & 1);          // key
            int c = (tid >> 5) + 8*(it >> 1);          // dim group
            float4 vv = *(const float4*)(Vp + (size_t)n*DHn + 4*c);
            float e[4] = {tf32r(vv.x), tf32r(vv.y), tf32r(vv.z), tf32r(vv.w)};
            #pragma unroll
            for (int z = 0; z < 4; z++) {
                int d = 4*c + z;
                Vt[d*64 + 4*((n >> 2) ^ (d & 7)) + (n & 3)] = e[z];
            }
        }
        __syncthreads();

        // ---- S = Q K^T ----
        float s[8][4] = {};
        #pragma unroll
        for (int kk = 0; kk < 8; kk++) {
            unsigned a0, a1, a2, a3;
            ldsm4(a0, a1, a2, a3, aQb + kk*32);
            #pragma unroll
            for (int p = 0; p < 4; p++) {
                unsigned b0, b1, b2, b3;
                ldsm4(b0, b1, b2, b3, bKb[p] + kk*32);
                mma_tf32(s[2*p],   a0, a1, a2, a3, b0, b1);
                mma_tf32(s[2*p+1], a0, a1, a2, a3, b2, b3);
            }
        }

        // ---- mask (bit-packed) + row max ----
        const unsigned* Mb0 = g_mbits + (size_t)(q0 + r0)*(Tn/32) + (j0 >> 5);
        const unsigned* Mb1 = Mb0 + (size_t)8*(Tn/32);
        unsigned w0a = Mb0[0], w0b = Mb0[1];
        unsigned w1a = Mb1[0], w1b = Mb1[1];
        float mx0 = -1e30f, mx1 = -1e30f;
        #pragma unroll
        for (int nt = 0; nt < 8; nt++) {
            unsigned wr0 = (nt < 4) ? w0a : w0b;
            unsigned wr1 = (nt < 4) ? w1a : w1b;
            int sh = (nt & 3)*8 + 2*tg;
            if (!((wr0 >> sh) & 1))       s[nt][0] -= 1e9f;
            if (!((wr0 >> (sh+1)) & 1))   s[nt][1] -= 1e9f;
            if (!((wr1 >> sh) & 1))       s[nt][2] -= 1e9f;
            if (!((wr1 >> (sh+1)) & 1))   s[nt][3] -= 1e9f;
            mx0 = fmaxf(mx0, fmaxf(s[nt][0], s[nt][1]));
            mx1 = fmaxf(mx1, fmaxf(s[nt][2], s[nt][3]));
        }
        mx0 = fmaxf(mx0, __shfl_xor_sync(0xffffffffu, mx0, 1));
        mx0 = fmaxf(mx0, __shfl_xor_sync(0xffffffffu, mx0, 2));
        mx1 = fmaxf(mx1, __shfl_xor_sync(0xffffffffu, mx1, 1));
        mx1 = fmaxf(mx1, __shfl_xor_sync(0xffffffffu, mx1, 2));

        float mn0 = fmaxf(m0r, mx0), mn1 = fmaxf(m1r, mx1);

        // ---- exp (P stays in registers), partial row sums ----
        float l0 = 0.0f, l1 = 0.0f;
        #pragma unroll
        for (int nt = 0; nt < 8; nt++) {
            s[nt][0] = __expf(s[nt][0] - mn0);
            s[nt][1] = __expf(s[nt][1] - mn0);
            s[nt][2] = __expf(s[nt][2] - mn1);
            s[nt][3] = __expf(s[nt][3] - mn1);
            l0 += s[nt][0] + s[nt][1];
            l1 += s[nt][2] + s[nt][3];
        }
        l0 += __shfl_xor_sync(0xffffffffu, l0, 1);
        l0 += __shfl_xor_sync(0xffffffffu, l0, 2);
        l1 += __shfl_xor_sync(0xffffffffu, l1, 1);
        l1 += __shfl_xor_sync(0xffffffffu, l1, 2);

        float c0 = __expf(m0r - mn0);
        float c1 = __expf(m1r - mn1);
        m0r = mn0; m1r = mn1;
        l0r = l0r*c0 + l0;
        l1r = l1r*c1 + l1;

        // ---- O = O*corr + P V ; P A-frags built by shfl from S C-frags ----
        #pragma unroll
        for (int nt = 0; nt < 8; nt++) {
            o[nt][0] *= c0; o[nt][1] *= c0;
            o[nt][2] *= c1; o[nt][3] *= c1;
        }
        const int src1 = (lane & 28) | (tg >> 1);
        const int src2 = src1 | 2;
        const bool odd = tg & 1;
        #pragma unroll
        for (int kk = 0; kk < 8; kk++) {
            float v0 = __shfl_sync(0xffffffffu, s[kk][0], src1);
            float v1 = __shfl_sync(0xffffffffu, s[kk][1], src1);
            float v2 = __shfl_sync(0xffffffffu, s[kk][2], src1);
            float v3 = __shfl_sync(0xffffffffu, s[kk][3], src1);
            float u0 = __shfl_sync(0xffffffffu, s[kk][0], src2);
            float u1 = __shfl_sync(0xffffffffu, s[kk][1], src2);
            float u2 = __shfl_sync(0xffffffffu, s[kk][2], src2);
            float u3 = __shfl_sync(0xffffffffu, s[kk][3], src2);
            unsigned a0 = fbits(tf32r(odd ? v1 : v0));
            unsigned a1 = fbits(tf32r(odd ? v3 : v2));
            unsigned a2 = fbits(tf32r(odd ? u1 : u0));
            unsigned a3 = fbits(tf32r(odd ? u3 : u2));
            #pragma unroll
            for (int p = 0; p < 4; p++) {
                unsigned b0, b1, b2, b3;
                unsigned ofs = (unsigned)(((2*kk + c01) ^ eV[p]) << 4);
                ldsm4(b0, b1, b2, b3, bVb[p] + ofs);
                mma_tf32(o[2*p],   a0, a1, a2, a3, b0, b1);
                mma_tf32(o[2*p+1], a0, a1, a2, a3, b2, b3);
            }
        }
    }

    // ---- finalize: normalize, write head-interleaved [b][t][d] ----
    const int b = bh >> 3, h = bh & 7;
    float inv0 = 1.0f / l0r;
    float inv1 = 1.0f / l1r;
    float* O0 = g_AO + ((size_t)(b*Tn + q0 + r0))*Dn + h*DHn;
    float* O1 = g_AO + ((size_t)(b*Tn + q0 + r1))*Dn + h*DHn;
    #pragma unroll
    for (int nt = 0; nt < 8; nt++) {
        int col = nt*8 + 2*tg;
        *(float2*)(O0 + col) = make_float2(o[nt][0]*inv0, o[nt][1]*inv0);
        *(float2*)(O1 + col) = make_float2(o[nt][2]*inv1, o[nt][3]*inv1);
    }
}

// ---------------------------------------------------------------------------
extern "C" void kernel_launch(void* const* d_in, const int* in_sizes, int n_in,
                              void* d_out, int out_size)
{
    const float* x  = (const float*)d_in[0];
    const float* Wq = (const float*)d_in[1];
    const float* bq = (const float*)d_in[2];
    const float* Wk = (const float*)d_in[3];
    const float* bk = (const float*)d_in[4];
    const float* Wv = (const float*)d_in[5];
    const float* bv = (const float*)d_in[6];
    const float* Wo = (const float*)d_in[7];
    const float* bo = (const float*)d_in[8];
    const void*  mask = (const void*)d_in[9];
    float* out = (float*)d_out;

    const int attn_smem = (AQ*SQ + AK*SQ + AK*64) * 4;  // 68,608 B
    cudaFuncSetAttribute(attn_kernel, cudaFuncAttributeMaxDynamicSharedMemorySize, attn_smem);
    cudaFuncSetAttribute(qkv_gemm, cudaFuncAttributeMaxDynamicSharedMemorySize, GEMM_SMEM);
    cudaFuncSetAttribute(out_gemm, cudaFuncAttributeMaxDynamicSharedMemorySize, GEMM_SMEM);

    detect_mask<<<1, 32>>>(mask);
    convert_mask<<<2048, 256>>>(mask);
    qkv_gemm<<<dim3(Dn/64, (Bn*Tn)/128, 3), 256, GEMM_SMEM>>>(x, Wq, Wk, Wv, bq, bk, bv);
    attn_kernel<<<dim3(Tn/AQ, BHn), 256, attn_smem>>>();
    out_gemm<<<dim3(Dn/64, (Bn*Tn)/128), 256, GEMM_SMEM>>>(Wo, bo, out);
}